// round 1
// baseline (speedup 1.0000x reference)
#include <cuda_runtime.h>
#include <math_constants.h>

#define NN 50000
#define NE 800000
#define NEE 850000          // NE + NN self loops
#define DD 128
#define HH 4

// ---- scratch (device globals; no allocations allowed) ----
__device__ float g_xl[NN * DD];
__device__ float g_xr[NN * DD];
__device__ float g_res[NN * DD];
__device__ float g_h[NN * DD];
__device__ int   g_rowptr[NN + 1];
__device__ int   g_cnt[NN];
__device__ int   g_off[NN];
__device__ int   g_csrc[NEE];

// ============================ CSR build ============================

__global__ void zero_cnt_kernel() {
    int i = blockIdx.x * blockDim.x + threadIdx.x;
    if (i < NN) g_cnt[i] = 0;
}

__global__ void hist_kernel(const int* __restrict__ ei) {
    int e = blockIdx.x * blockDim.x + threadIdx.x;
    if (e >= NEE) return;
    int dst = (e < NE) ? ei[NE + e] : (e - NE);
    atomicAdd(&g_cnt[dst], 1);
}

// single-block exclusive scan over g_cnt -> g_rowptr, g_off
__global__ void scan_kernel() {
    __shared__ int sh[1024];
    int tid = threadIdx.x;
    int carry = 0;
    for (int base = 0; base < NN; base += 1024) {
        int i = base + tid;
        int v = (i < NN) ? g_cnt[i] : 0;
        sh[tid] = v;
        __syncthreads();
        #pragma unroll
        for (int o = 1; o < 1024; o <<= 1) {
            int t = (tid >= o) ? sh[tid - o] : 0;
            __syncthreads();
            sh[tid] += t;
            __syncthreads();
        }
        int incl = sh[tid];
        int excl = incl - v + carry;
        if (i < NN) { g_rowptr[i] = excl; g_off[i] = excl; }
        carry += sh[1023];
        __syncthreads();
    }
    if (tid == 0) g_rowptr[NN] = carry;
}

__global__ void scatter_kernel(const int* __restrict__ ei) {
    int e = blockIdx.x * blockDim.x + threadIdx.x;
    if (e >= NEE) return;
    int src, dst;
    if (e < NE) { src = ei[e]; dst = ei[NE + e]; }
    else        { src = e - NE; dst = e - NE; }
    int pos = atomicAdd(&g_off[dst], 1);
    g_csrc[pos] = src;
}

// ============================ GEMM (fp32) ============================
// out[m][n] = sum_k x[m][k] * W[k][n] + b[n]
// block: 256 threads, M-tile 64, full N=128, K chunks of 16.

#define BM 64
#define BK 16

__global__ void gemm_kernel(const float* __restrict__ xin,
                            const float* __restrict__ W,
                            const float* __restrict__ b,
                            int out_sel) {
    const float* x = xin ? xin : g_h;
    float* out = (out_sel == 0) ? g_xl : (out_sel == 1) ? g_xr : g_res;

    __shared__ float xs[BM][BK];
    __shared__ float ws[BK][DD];

    int tid  = threadIdx.x;
    int m0   = blockIdx.x * BM;
    int colt = tid & 31;   // col lane: cols colt + 32*j
    int rowt = tid >> 5;   // 0..7: rows rowt*8 + r

    float acc[8][4];
    #pragma unroll
    for (int r = 0; r < 8; r++)
        #pragma unroll
        for (int j = 0; j < 4; j++) acc[r][j] = 0.f;

    for (int kc = 0; kc < DD; kc += BK) {
        // load x tile: 64x16 floats = 256 float4 (one per thread)
        {
            int r = tid >> 2;
            int v = tid & 3;
            int m = m0 + r;
            float4 val = make_float4(0.f, 0.f, 0.f, 0.f);
            if (m < NN)
                val = *reinterpret_cast<const float4*>(&x[m * DD + kc + v * 4]);
            *reinterpret_cast<float4*>(&xs[r][v * 4]) = val;
        }
        // load W tile: 16x128 floats = 512 float4 (two per thread)
        #pragma unroll
        for (int t = 0; t < 2; t++) {
            int f  = tid + t * 256;
            int k  = f >> 5;
            int c4 = f & 31;
            float4 val = *reinterpret_cast<const float4*>(&W[(kc + k) * DD + c4 * 4]);
            *reinterpret_cast<float4*>(&ws[k][c4 * 4]) = val;
        }
        __syncthreads();

        #pragma unroll
        for (int k = 0; k < BK; k++) {
            float wv[4];
            #pragma unroll
            for (int j = 0; j < 4; j++) wv[j] = ws[k][colt + 32 * j];
            #pragma unroll
            for (int r = 0; r < 8; r++) {
                float xv = xs[rowt * 8 + r][k];
                #pragma unroll
                for (int j = 0; j < 4; j++)
                    acc[r][j] = fmaf(xv, wv[j], acc[r][j]);
            }
        }
        __syncthreads();
    }

    #pragma unroll
    for (int r = 0; r < 8; r++) {
        int m = m0 + rowt * 8 + r;
        if (m < NN) {
            #pragma unroll
            for (int j = 0; j < 4; j++) {
                int c = colt + 32 * j;
                out[m * DD + c] = acc[r][j] + b[c];
            }
        }
    }
}

// ================= fused edge kernel: online segment-softmax =================
// one warp per destination node; single pass over incoming edges;
// fused residual + LayerNorm + ReLU epilogue.

__global__ void edge_kernel(const float* __restrict__ att,
                            const float* __restrict__ gam,
                            const float* __restrict__ bet,
                            float* outp /* null -> g_h */) {
    float* out = outp ? outp : g_h;
    int warp = (blockIdx.x * blockDim.x + threadIdx.x) >> 5;
    int lane = threadIdx.x & 31;
    if (warp >= NN) return;
    int d = warp;

    float xrv[HH], av[HH];
    #pragma unroll
    for (int h = 0; h < HH; h++) {
        xrv[h] = g_xr[d * DD + h * 32 + lane];
        av[h]  = __ldg(&att[h * 32 + lane]);
    }

    float m[HH], s[HH], acc[HH];
    #pragma unroll
    for (int h = 0; h < HH; h++) { m[h] = -CUDART_INF_F; s[h] = 0.f; acc[h] = 0.f; }

    int e0 = g_rowptr[d], e1 = g_rowptr[d + 1];
    for (int e = e0; e < e1; e++) {
        int sn = g_csrc[e];
        const float* xp = g_xl + sn * DD;
        float v[HH];
        #pragma unroll
        for (int h = 0; h < HH; h++) v[h] = __ldg(&xp[h * 32 + lane]);

        float sc[HH];
        #pragma unroll
        for (int h = 0; h < HH; h++) {
            float t = v[h] + xrv[h];
            t = t > 0.f ? t : 0.2f * t;          // leaky relu 0.2
            float p = t * av[h];
            #pragma unroll
            for (int o = 16; o > 0; o >>= 1)
                p += __shfl_xor_sync(0xFFFFFFFFu, p, o);
            sc[h] = p;
        }
        #pragma unroll
        for (int h = 0; h < HH; h++) {
            float mn   = fmaxf(m[h], sc[h]);
            float cold = __expf(m[h] - mn);      // exp(-inf)=0 on first edge
            float ce   = __expf(sc[h] - mn);
            s[h]   = s[h] * cold + ce;
            acc[h] = acc[h] * cold + ce * v[h];
            m[h]   = mn;
        }
    }

    // residual + bias (precomputed in g_res), then LayerNorm + ReLU
    float o[HH];
    #pragma unroll
    for (int h = 0; h < HH; h++)
        o[h] = acc[h] / s[h] + g_res[d * DD + h * 32 + lane];

    float sum = o[0] + o[1] + o[2] + o[3];
    #pragma unroll
    for (int off = 16; off > 0; off >>= 1)
        sum += __shfl_xor_sync(0xFFFFFFFFu, sum, off);
    float mu = sum * (1.f / 128.f);

    float var = 0.f;
    #pragma unroll
    for (int h = 0; h < HH; h++) { float dl = o[h] - mu; var += dl * dl; }
    #pragma unroll
    for (int off = 16; off > 0; off >>= 1)
        var += __shfl_xor_sync(0xFFFFFFFFu, var, off);
    var *= (1.f / 128.f);
    float rs = rsqrtf(var + 1e-5f);

    #pragma unroll
    for (int h = 0; h < HH; h++) {
        int c = h * 32 + lane;
        float y = (o[h] - mu) * rs * gam[c] + bet[c];
        out[d * DD + c] = fmaxf(y, 0.f);
    }
}

// ============================ launch ============================

extern "C" void kernel_launch(void* const* d_in, const int* in_sizes, int n_in,
                              void* d_out, int out_size) {
    const float* x     = (const float*)d_in[0];
    const int*   ei    = (const int*)  d_in[1];
    const float* Wl0   = (const float*)d_in[2];
    const float* bl0   = (const float*)d_in[3];
    const float* Wr0   = (const float*)d_in[4];
    const float* br0   = (const float*)d_in[5];
    const float* att0  = (const float*)d_in[6];
    const float* Wres0 = (const float*)d_in[7];
    const float* bias0 = (const float*)d_in[8];
    const float* g0    = (const float*)d_in[9];
    const float* be0   = (const float*)d_in[10];
    const float* Wl1   = (const float*)d_in[11];
    const float* bl1   = (const float*)d_in[12];
    const float* Wr1   = (const float*)d_in[13];
    const float* br1   = (const float*)d_in[14];
    const float* att1  = (const float*)d_in[15];
    const float* Wres1 = (const float*)d_in[16];
    const float* bias1 = (const float*)d_in[17];
    const float* g1    = (const float*)d_in[18];
    const float* be1   = (const float*)d_in[19];
    float* out = (float*)d_out;

    // CSR build (shared by both layers)
    zero_cnt_kernel<<<(NN + 255) / 256, 256>>>();
    hist_kernel<<<(NEE + 255) / 256, 256>>>(ei);
    scan_kernel<<<1, 1024>>>();
    scatter_kernel<<<(NEE + 255) / 256, 256>>>(ei);

    int gb = (NN + BM - 1) / BM;
    int eb = NN / 8;  // 8 warps per block, exact

    // layer 0 (input: external x, output: g_h)
    gemm_kernel<<<gb, 256>>>(x, Wl0,   bl0,   0);
    gemm_kernel<<<gb, 256>>>(x, Wr0,   br0,   1);
    gemm_kernel<<<gb, 256>>>(x, Wres0, bias0, 2);
    edge_kernel<<<eb, 256>>>(att0, g0, be0, nullptr);

    // layer 1 (input: g_h, output: d_out)
    gemm_kernel<<<gb, 256>>>(nullptr, Wl1,   bl1,   0);
    gemm_kernel<<<gb, 256>>>(nullptr, Wr1,   br1,   1);
    gemm_kernel<<<gb, 256>>>(nullptr, Wres1, bias1, 2);
    edge_kernel<<<eb, 256>>>(att1, g1, be1, out);
}

// round 2
// speedup vs baseline: 1.5754x; 1.5754x over previous
#include <cuda_runtime.h>
#include <math_constants.h>

#define NN 50000
#define NE 800000
#define NEE 850000          // NE + NN self loops
#define DD 128
#define HH 4

// ---- scratch (device globals; no allocations allowed) ----
__device__ float g_xl[NN * DD];
__device__ float g_xr[NN * DD];
__device__ float g_res[NN * DD];
__device__ float g_h[NN * DD];
__device__ int   g_rowptr[NN + 1];
__device__ int   g_cnt[NN];
__device__ int   g_off[NN];
__device__ int   g_csrc[NEE];
__device__ int   g_bsum[32];
__device__ int   g_boff[32];

// ============================ CSR build ============================

__global__ void zero_cnt_kernel() {
    int i = blockIdx.x * blockDim.x + threadIdx.x;
    if (i < NN) g_cnt[i] = 0;
}

__global__ void hist_kernel(const int* __restrict__ ei) {
    int e = blockIdx.x * blockDim.x + threadIdx.x;
    if (e >= NEE) return;
    int dst = (e < NE) ? ei[NE + e] : (e - NE);
    atomicAdd(&g_cnt[dst], 1);
}

// phase 1: per-block (2048 elems) exclusive scan, block totals to g_bsum
__global__ void scan1_kernel() {
    __shared__ int sh[1024];
    int tid = threadIdx.x;
    int base = blockIdx.x * 2048;
    int i0 = base + 2 * tid;
    int a = (i0     < NN) ? g_cnt[i0]     : 0;
    int b = (i0 + 1 < NN) ? g_cnt[i0 + 1] : 0;
    int pair = a + b;
    sh[tid] = pair;
    __syncthreads();
    #pragma unroll
    for (int o = 1; o < 1024; o <<= 1) {
        int t = (tid >= o) ? sh[tid - o] : 0;
        __syncthreads();
        sh[tid] += t;
        __syncthreads();
    }
    int excl = sh[tid] - pair;
    if (i0     < NN) g_rowptr[i0]     = excl;
    if (i0 + 1 < NN) g_rowptr[i0 + 1] = excl + a;
    if (tid == 1023) g_bsum[blockIdx.x] = sh[1023];
}

// phase 2: one warp scans the block totals (NB blocks)
__global__ void scan2_kernel(int nb) {
    int lane = threadIdx.x;
    int v = (lane < nb) ? g_bsum[lane] : 0;
    int orig = v;
    #pragma unroll
    for (int o = 1; o < 32; o <<= 1) {
        int t = __shfl_up_sync(0xFFFFFFFFu, v, o);
        if (lane >= o) v += t;
    }
    if (lane < nb) g_boff[lane] = v - orig;
    if (lane == nb - 1) g_rowptr[NN] = v;
}

// phase 3: add block offsets, copy to g_off
__global__ void scan3_kernel() {
    int i = blockIdx.x * blockDim.x + threadIdx.x;
    if (i >= NN) return;
    int r = g_rowptr[i] + g_boff[i >> 11];
    g_rowptr[i] = r;
    g_off[i] = r;
}

__global__ void scatter_kernel(const int* __restrict__ ei) {
    int e = blockIdx.x * blockDim.x + threadIdx.x;
    if (e >= NEE) return;
    int src, dst;
    if (e < NE) { src = ei[e]; dst = ei[NE + e]; }
    else        { src = e - NE; dst = e - NE; }
    int pos = atomicAdd(&g_off[dst], 1);
    g_csrc[pos] = src;
}

// ==================== fused triple GEMM (tf32 tensor core) ====================
// out[m][n] = sum_k x[m][k] * W[k][n] + b[n] for three weight sets per layer.
// grid.y selects (Wl -> g_xl) / (Wr -> g_xr) / (Wres -> g_res).
// block: 256 thr (8 warps, 4Mx2N), M-tile 128, N=128, K chunks of 32.

#define GM 128
#define GK 32
#define XS_STR 36     // 32 + 4 pad: A-frag reads conflict-free
#define WS_STR 136    // 128 + 8 pad: B-frag reads conflict-free

__device__ __forceinline__ unsigned f2tf32(float x) {
    unsigned u;
    asm("cvt.rna.tf32.f32 %0, %1;" : "=r"(u) : "f"(x));
    return u;
}

__device__ __forceinline__ void mma_tf32(float* d, const unsigned* a, const unsigned* b) {
    asm volatile(
        "mma.sync.aligned.m16n8k8.row.col.f32.tf32.tf32.f32 "
        "{%0,%1,%2,%3}, {%4,%5,%6,%7}, {%8,%9}, {%0,%1,%2,%3};"
        : "+f"(d[0]), "+f"(d[1]), "+f"(d[2]), "+f"(d[3])
        : "r"(a[0]), "r"(a[1]), "r"(a[2]), "r"(a[3]), "r"(b[0]), "r"(b[1]));
}

__global__ void __launch_bounds__(256, 2)
gemm3_kernel(const float* __restrict__ xin,
             const float* __restrict__ W0, const float* __restrict__ b0,
             const float* __restrict__ W1, const float* __restrict__ b1,
             const float* __restrict__ W2, const float* __restrict__ b2) {
    const float* x = xin ? xin : g_h;
    const float* W;
    const float* bias;
    float* out;
    if (blockIdx.y == 0)      { W = W0; bias = b0; out = g_xl; }
    else if (blockIdx.y == 1) { W = W1; bias = b1; out = g_xr; }
    else                      { W = W2; bias = b2; out = g_res; }

    __shared__ float xs[GM][XS_STR];
    __shared__ float ws[GK][WS_STR];

    int tid  = threadIdx.x;
    int lane = tid & 31;
    int wid  = tid >> 5;
    int wm   = wid & 3;        // warp M position (4)
    int wn   = wid >> 2;       // warp N position (2)
    int g    = lane >> 2;      // groupID
    int t4   = lane & 3;       // thread in group
    int m0   = blockIdx.x * GM;

    float acc[2][8][4];
    #pragma unroll
    for (int mt = 0; mt < 2; mt++)
        #pragma unroll
        for (int nt = 0; nt < 8; nt++)
            #pragma unroll
            for (int i = 0; i < 4; i++) acc[mt][nt][i] = 0.f;

    for (int kc = 0; kc < DD; kc += GK) {
        // load x tile 128x32: 1024 float4, 4 per thread (tf32-rounded)
        #pragma unroll
        for (int t = 0; t < 4; t++) {
            int f   = tid + t * 256;
            int row = f >> 3;
            int c4  = f & 7;
            int m   = m0 + row;
            float4 v = make_float4(0.f, 0.f, 0.f, 0.f);
            if (m < NN)
                v = *reinterpret_cast<const float4*>(&x[m * DD + kc + c4 * 4]);
            float* dst = &xs[row][c4 * 4];
            dst[0] = __uint_as_float(f2tf32(v.x));
            dst[1] = __uint_as_float(f2tf32(v.y));
            dst[2] = __uint_as_float(f2tf32(v.z));
            dst[3] = __uint_as_float(f2tf32(v.w));
        }
        // load W tile 32x128: 1024 float4, 4 per thread
        #pragma unroll
        for (int t = 0; t < 4; t++) {
            int f   = tid + t * 256;
            int row = f >> 5;
            int c4  = f & 31;
            float4 v = *reinterpret_cast<const float4*>(&W[(kc + row) * DD + c4 * 4]);
            float* dst = &ws[row][c4 * 4];
            dst[0] = __uint_as_float(f2tf32(v.x));
            dst[1] = __uint_as_float(f2tf32(v.y));
            dst[2] = __uint_as_float(f2tf32(v.z));
            dst[3] = __uint_as_float(f2tf32(v.w));
        }
        __syncthreads();

        #pragma unroll
        for (int ks = 0; ks < GK; ks += 8) {
            unsigned A[2][4];
            #pragma unroll
            for (int mt = 0; mt < 2; mt++) {
                int r0 = wm * 32 + mt * 16;
                A[mt][0] = __float_as_uint(xs[r0 + g    ][ks + t4    ]);
                A[mt][1] = __float_as_uint(xs[r0 + 8 + g][ks + t4    ]);
                A[mt][2] = __float_as_uint(xs[r0 + g    ][ks + t4 + 4]);
                A[mt][3] = __float_as_uint(xs[r0 + 8 + g][ks + t4 + 4]);
            }
            unsigned B[8][2];
            #pragma unroll
            for (int nt = 0; nt < 8; nt++) {
                int c0 = wn * 64 + nt * 8 + g;
                B[nt][0] = __float_as_uint(ws[ks + t4    ][c0]);
                B[nt][1] = __float_as_uint(ws[ks + t4 + 4][c0]);
            }
            #pragma unroll
            for (int mt = 0; mt < 2; mt++)
                #pragma unroll
                for (int nt = 0; nt < 8; nt++)
                    mma_tf32(acc[mt][nt], A[mt], B[nt]);
        }
        __syncthreads();
    }

    // epilogue: add bias, store
    #pragma unroll
    for (int mt = 0; mt < 2; mt++) {
        #pragma unroll
        for (int nt = 0; nt < 8; nt++) {
            int r = m0 + wm * 32 + mt * 16 + g;
            int c = wn * 64 + nt * 8 + t4 * 2;
            float bv0 = bias[c], bv1 = bias[c + 1];
            if (r < NN) {
                out[r * DD + c]     = acc[mt][nt][0] + bv0;
                out[r * DD + c + 1] = acc[mt][nt][1] + bv1;
            }
            if (r + 8 < NN) {
                out[(r + 8) * DD + c]     = acc[mt][nt][2] + bv0;
                out[(r + 8) * DD + c + 1] = acc[mt][nt][3] + bv1;
            }
        }
    }
}

// ================= fused edge kernel: online segment-softmax =================

__global__ void edge_kernel(const float* __restrict__ att,
                            const float* __restrict__ gam,
                            const float* __restrict__ bet,
                            float* outp /* null -> g_h */) {
    float* out = outp ? outp : g_h;
    int warp = (blockIdx.x * blockDim.x + threadIdx.x) >> 5;
    int lane = threadIdx.x & 31;
    if (warp >= NN) return;
    int d = warp;

    float xrv[HH], av[HH];
    #pragma unroll
    for (int h = 0; h < HH; h++) {
        xrv[h] = g_xr[d * DD + h * 32 + lane];
        av[h]  = __ldg(&att[h * 32 + lane]);
    }

    float m[HH], s[HH], acc[HH];
    #pragma unroll
    for (int h = 0; h < HH; h++) { m[h] = -CUDART_INF_F; s[h] = 0.f; acc[h] = 0.f; }

    int e0 = g_rowptr[d], e1 = g_rowptr[d + 1];
    for (int e = e0; e < e1; e++) {
        int sn = g_csrc[e];
        const float* xp = g_xl + sn * DD;
        float v[HH];
        #pragma unroll
        for (int h = 0; h < HH; h++) v[h] = __ldg(&xp[h * 32 + lane]);

        float sc[HH];
        #pragma unroll
        for (int h = 0; h < HH; h++) {
            float t = v[h] + xrv[h];
            t = t > 0.f ? t : 0.2f * t;          // leaky relu 0.2
            float p = t * av[h];
            #pragma unroll
            for (int o = 16; o > 0; o >>= 1)
                p += __shfl_xor_sync(0xFFFFFFFFu, p, o);
            sc[h] = p;
        }
        #pragma unroll
        for (int h = 0; h < HH; h++) {
            float mn   = fmaxf(m[h], sc[h]);
            float cold = __expf(m[h] - mn);      // exp(-inf)=0 on first edge
            float ce   = __expf(sc[h] - mn);
            s[h]   = s[h] * cold + ce;
            acc[h] = acc[h] * cold + ce * v[h];
            m[h]   = mn;
        }
    }

    float o[HH];
    #pragma unroll
    for (int h = 0; h < HH; h++)
        o[h] = acc[h] / s[h] + g_res[d * DD + h * 32 + lane];

    float sum = o[0] + o[1] + o[2] + o[3];
    #pragma unroll
    for (int off = 16; off > 0; off >>= 1)
        sum += __shfl_xor_sync(0xFFFFFFFFu, sum, off);
    float mu = sum * (1.f / 128.f);

    float var = 0.f;
    #pragma unroll
    for (int h = 0; h < HH; h++) { float dl = o[h] - mu; var += dl * dl; }
    #pragma unroll
    for (int off = 16; off > 0; off >>= 1)
        var += __shfl_xor_sync(0xFFFFFFFFu, var, off);
    var *= (1.f / 128.f);
    float rs = rsqrtf(var + 1e-5f);

    #pragma unroll
    for (int h = 0; h < HH; h++) {
        int c = h * 32 + lane;
        float y = (o[h] - mu) * rs * gam[c] + bet[c];
        out[d * DD + c] = fmaxf(y, 0.f);
    }
}

// ============================ launch ============================

extern "C" void kernel_launch(void* const* d_in, const int* in_sizes, int n_in,
                              void* d_out, int out_size) {
    const float* x     = (const float*)d_in[0];
    const int*   ei    = (const int*)  d_in[1];
    const float* Wl0   = (const float*)d_in[2];
    const float* bl0   = (const float*)d_in[3];
    const float* Wr0   = (const float*)d_in[4];
    const float* br0   = (const float*)d_in[5];
    const float* att0  = (const float*)d_in[6];
    const float* Wres0 = (const float*)d_in[7];
    const float* bias0 = (const float*)d_in[8];
    const float* g0    = (const float*)d_in[9];
    const float* be0   = (const float*)d_in[10];
    const float* Wl1   = (const float*)d_in[11];
    const float* bl1   = (const float*)d_in[12];
    const float* Wr1   = (const float*)d_in[13];
    const float* br1   = (const float*)d_in[14];
    const float* att1  = (const float*)d_in[15];
    const float* Wres1 = (const float*)d_in[16];
    const float* bias1 = (const float*)d_in[17];
    const float* g1    = (const float*)d_in[18];
    const float* be1   = (const float*)d_in[19];
    float* out = (float*)d_out;

    // CSR build (shared by both layers)
    const int NB = (NN + 2047) / 2048;   // 25
    zero_cnt_kernel<<<(NN + 255) / 256, 256>>>();
    hist_kernel<<<(NEE + 255) / 256, 256>>>(ei);
    scan1_kernel<<<NB, 1024>>>();
    scan2_kernel<<<1, 32>>>(NB);
    scan3_kernel<<<(NN + 255) / 256, 256>>>();
    scatter_kernel<<<(NEE + 255) / 256, 256>>>(ei);

    dim3 gb((NN + GM - 1) / GM, 3);
    int eb = NN / 8;  // 8 warps per block, exact

    // layer 0 (input: external x, output: g_h)
    gemm3_kernel<<<gb, 256>>>(x, Wl0, bl0, Wr0, br0, Wres0, bias0);
    edge_kernel<<<eb, 256>>>(att0, g0, be0, nullptr);

    // layer 1 (input: g_h, output: d_out)
    gemm3_kernel<<<gb, 256>>>(nullptr, Wl1, bl1, Wr1, br1, Wres1, bias1);
    edge_kernel<<<eb, 256>>>(att1, g1, be1, out);
}

// round 3
// speedup vs baseline: 1.9294x; 1.2247x over previous
#include <cuda_runtime.h>
#include <math_constants.h>

#define NN 50000
#define NE 800000
#define NEE 850000          // NE + NN self loops
#define DD 128
#define HH 4

// ---- scratch (device globals; no allocations allowed) ----
// g_xl, g_xr, g_res are stored HEAD-INTERLEAVED: element (h, c) at offset c*4 + h.
__device__ float g_xl[NN * DD];
__device__ float g_xr[NN * DD];
__device__ float g_res[NN * DD];
__device__ float g_h[NN * DD];     // standard layout (feeds next GEMM / matches x)
__device__ int   g_rowptr[NN + 1];
__device__ int   g_cnt[NN];
__device__ int   g_off[NN];
__device__ int   g_csrc[NEE];
__device__ int   g_bsum[32];
__device__ int   g_boff[32];

// ============================ CSR build ============================

__global__ void zero_cnt_kernel() {
    int i = blockIdx.x * blockDim.x + threadIdx.x;
    if (i < NN) g_cnt[i] = 0;
}

__global__ void hist_kernel(const int* __restrict__ ei) {
    int e = blockIdx.x * blockDim.x + threadIdx.x;
    if (e >= NEE) return;
    int dst = (e < NE) ? ei[NE + e] : (e - NE);
    atomicAdd(&g_cnt[dst], 1);
}

__global__ void scan1_kernel() {
    __shared__ int sh[1024];
    int tid = threadIdx.x;
    int base = blockIdx.x * 2048;
    int i0 = base + 2 * tid;
    int a = (i0     < NN) ? g_cnt[i0]     : 0;
    int b = (i0 + 1 < NN) ? g_cnt[i0 + 1] : 0;
    int pair = a + b;
    sh[tid] = pair;
    __syncthreads();
    #pragma unroll
    for (int o = 1; o < 1024; o <<= 1) {
        int t = (tid >= o) ? sh[tid - o] : 0;
        __syncthreads();
        sh[tid] += t;
        __syncthreads();
    }
    int excl = sh[tid] - pair;
    if (i0     < NN) g_rowptr[i0]     = excl;
    if (i0 + 1 < NN) g_rowptr[i0 + 1] = excl + a;
    if (tid == 1023) g_bsum[blockIdx.x] = sh[1023];
}

__global__ void scan2_kernel(int nb) {
    int lane = threadIdx.x;
    int v = (lane < nb) ? g_bsum[lane] : 0;
    int orig = v;
    #pragma unroll
    for (int o = 1; o < 32; o <<= 1) {
        int t = __shfl_up_sync(0xFFFFFFFFu, v, o);
        if (lane >= o) v += t;
    }
    if (lane < nb) g_boff[lane] = v - orig;
    if (lane == nb - 1) g_rowptr[NN] = v;
}

__global__ void scan3_kernel() {
    int i = blockIdx.x * blockDim.x + threadIdx.x;
    if (i >= NN) return;
    int r = g_rowptr[i] + g_boff[i >> 11];
    g_rowptr[i] = r;
    g_off[i] = r;
}

__global__ void scatter_kernel(const int* __restrict__ ei) {
    int e = blockIdx.x * blockDim.x + threadIdx.x;
    if (e >= NEE) return;
    int src, dst;
    if (e < NE) { src = ei[e]; dst = ei[NE + e]; }
    else        { src = e - NE; dst = e - NE; }
    int pos = atomicAdd(&g_off[dst], 1);
    g_csrc[pos] = src;
}

// ==================== fused triple GEMM (tf32 tensor core) ====================
// Computes out_perm = x @ W_perm + b_perm where W's columns are permuted at
// smem-load time into head-interleaved order: pc(c) = (c&31)*4 + (c>>5).
// Output stores keep the original coalesced pattern -> data lands permuted.

#define GM 128
#define GK 32
#define XS_STR 36     // 32 + 4 pad
#define WS_STR 136    // 128 + 8 pad

__device__ __forceinline__ unsigned f2tf32(float x) {
    unsigned u;
    asm("cvt.rna.tf32.f32 %0, %1;" : "=r"(u) : "f"(x));
    return u;
}

__device__ __forceinline__ void mma_tf32(float* d, const unsigned* a, const unsigned* b) {
    asm volatile(
        "mma.sync.aligned.m16n8k8.row.col.f32.tf32.tf32.f32 "
        "{%0,%1,%2,%3}, {%4,%5,%6,%7}, {%8,%9}, {%0,%1,%2,%3};"
        : "+f"(d[0]), "+f"(d[1]), "+f"(d[2]), "+f"(d[3])
        : "r"(a[0]), "r"(a[1]), "r"(a[2]), "r"(a[3]), "r"(b[0]), "r"(b[1]));
}

__global__ void __launch_bounds__(256, 2)
gemm3_kernel(const float* __restrict__ xin,
             const float* __restrict__ W0, const float* __restrict__ b0,
             const float* __restrict__ W1, const float* __restrict__ b1,
             const float* __restrict__ W2, const float* __restrict__ b2) {
    const float* x = xin ? xin : g_h;
    const float* W;
    const float* bias;
    float* out;
    if (blockIdx.y == 0)      { W = W0; bias = b0; out = g_xl; }
    else if (blockIdx.y == 1) { W = W1; bias = b1; out = g_xr; }
    else                      { W = W2; bias = b2; out = g_res; }

    __shared__ float xs[GM][XS_STR];
    __shared__ float ws[GK][WS_STR];

    int tid  = threadIdx.x;
    int lane = tid & 31;
    int wid  = tid >> 5;
    int wm   = wid & 3;
    int wn   = wid >> 2;
    int g    = lane >> 2;
    int t4   = lane & 3;
    int m0   = blockIdx.x * GM;

    float acc[2][8][4];
    #pragma unroll
    for (int mt = 0; mt < 2; mt++)
        #pragma unroll
        for (int nt = 0; nt < 8; nt++)
            #pragma unroll
            for (int i = 0; i < 4; i++) acc[mt][nt][i] = 0.f;

    for (int kc = 0; kc < DD; kc += GK) {
        // x tile 128x32
        #pragma unroll
        for (int t = 0; t < 4; t++) {
            int f   = tid + t * 256;
            int row = f >> 3;
            int c4  = f & 7;
            int m   = m0 + row;
            float4 v = make_float4(0.f, 0.f, 0.f, 0.f);
            if (m < NN)
                v = *reinterpret_cast<const float4*>(&x[m * DD + kc + c4 * 4]);
            float* dst = &xs[row][c4 * 4];
            dst[0] = __uint_as_float(f2tf32(v.x));
            dst[1] = __uint_as_float(f2tf32(v.y));
            dst[2] = __uint_as_float(f2tf32(v.z));
            dst[3] = __uint_as_float(f2tf32(v.w));
        }
        // W tile 32x128, columns permuted into head-interleaved order
        #pragma unroll
        for (int t = 0; t < 4; t++) {
            int f   = tid + t * 256;
            int row = f >> 5;
            int c4  = f & 31;
            float4 v = *reinterpret_cast<const float4*>(&W[(kc + row) * DD + c4 * 4]);
            int cb = c4 * 4;
            int blk = cb >> 5;            // same for all 4 elements
            int bas = (cb & 31) * 4 + blk;
            ws[row][bas     ] = __uint_as_float(f2tf32(v.x));
            ws[row][bas + 4 ] = __uint_as_float(f2tf32(v.y));
            ws[row][bas + 8 ] = __uint_as_float(f2tf32(v.z));
            ws[row][bas + 12] = __uint_as_float(f2tf32(v.w));
        }
        __syncthreads();

        #pragma unroll
        for (int ks = 0; ks < GK; ks += 8) {
            unsigned A[2][4];
            #pragma unroll
            for (int mt = 0; mt < 2; mt++) {
                int r0 = wm * 32 + mt * 16;
                A[mt][0] = __float_as_uint(xs[r0 + g    ][ks + t4    ]);
                A[mt][1] = __float_as_uint(xs[r0 + 8 + g][ks + t4    ]);
                A[mt][2] = __float_as_uint(xs[r0 + g    ][ks + t4 + 4]);
                A[mt][3] = __float_as_uint(xs[r0 + 8 + g][ks + t4 + 4]);
            }
            unsigned B[8][2];
            #pragma unroll
            for (int nt = 0; nt < 8; nt++) {
                int c0 = wn * 64 + nt * 8 + g;
                B[nt][0] = __float_as_uint(ws[ks + t4    ][c0]);
                B[nt][1] = __float_as_uint(ws[ks + t4 + 4][c0]);
            }
            #pragma unroll
            for (int mt = 0; mt < 2; mt++)
                #pragma unroll
                for (int nt = 0; nt < 8; nt++)
                    mma_tf32(acc[mt][nt], A[mt], B[nt]);
        }
        __syncthreads();
    }

    // epilogue: columns are permuted; bias via inverse perm c_orig = (j>>2) + (j&3)*32
    #pragma unroll
    for (int mt = 0; mt < 2; mt++) {
        #pragma unroll
        for (int nt = 0; nt < 8; nt++) {
            int r = m0 + wm * 32 + mt * 16 + g;
            int j = wn * 64 + nt * 8 + t4 * 2;
            float bv0 = bias[(j >> 2) + (j & 3) * 32];
            float bv1 = bias[((j + 1) >> 2) + ((j + 1) & 3) * 32];
            if (r < NN) {
                out[r * DD + j]     = acc[mt][nt][0] + bv0;
                out[r * DD + j + 1] = acc[mt][nt][1] + bv1;
            }
            if (r + 8 < NN) {
                out[(r + 8) * DD + j]     = acc[mt][nt][2] + bv0;
                out[(r + 8) * DD + j + 1] = acc[mt][nt][3] + bv1;
            }
        }
    }
}

// ================= fused edge kernel: segment softmax (no-max, bounded scores) ==
// one warp per destination node; head-interleaved gathers (1 LDG.128/lane/edge);
// unroll-2 for MLP; fused residual + LayerNorm + ReLU epilogue (standard layout out).

__device__ __forceinline__ float lrelu(float t) {
    return t > 0.f ? t : 0.2f * t;
}

__global__ void edge_kernel(const float* __restrict__ att,
                            const float* __restrict__ gam,
                            const float* __restrict__ bet,
                            float* outp /* null -> g_h */) {
    float* out = outp ? outp : g_h;
    int d = (blockIdx.x * blockDim.x + threadIdx.x) >> 5;
    int lane = threadIdx.x & 31;
    if (d >= NN) return;

    // per-node invariants (head-interleaved: .x..w = heads 0..3 at channel=lane)
    float4 xr = *reinterpret_cast<const float4*>(&g_xr[d * DD + lane * 4]);
    float av0 = __ldg(&att[lane]);
    float av1 = __ldg(&att[32 + lane]);
    float av2 = __ldg(&att[64 + lane]);
    float av3 = __ldg(&att[96 + lane]);

    float s0 = 0.f, s1 = 0.f, s2 = 0.f, s3 = 0.f;
    float a0 = 0.f, a1 = 0.f, a2 = 0.f, a3 = 0.f;

    int e0 = g_rowptr[d], e1 = g_rowptr[d + 1];
    int e = e0;
    for (; e + 2 <= e1; e += 2) {
        int sA = __ldg(&g_csrc[e]);
        int sB = __ldg(&g_csrc[e + 1]);
        float4 vA = __ldg(reinterpret_cast<const float4*>(&g_xl[sA * DD + lane * 4]));
        float4 vB = __ldg(reinterpret_cast<const float4*>(&g_xl[sB * DD + lane * 4]));

        float p[8];
        p[0] = lrelu(vA.x + xr.x) * av0;
        p[1] = lrelu(vA.y + xr.y) * av1;
        p[2] = lrelu(vA.z + xr.z) * av2;
        p[3] = lrelu(vA.w + xr.w) * av3;
        p[4] = lrelu(vB.x + xr.x) * av0;
        p[5] = lrelu(vB.y + xr.y) * av1;
        p[6] = lrelu(vB.z + xr.z) * av2;
        p[7] = lrelu(vB.w + xr.w) * av3;
        #pragma unroll
        for (int o = 16; o > 0; o >>= 1) {
            #pragma unroll
            for (int i = 0; i < 8; i++)
                p[i] += __shfl_xor_sync(0xFFFFFFFFu, p[i], o);
        }
        float cA0 = __expf(p[0]), cA1 = __expf(p[1]), cA2 = __expf(p[2]), cA3 = __expf(p[3]);
        float cB0 = __expf(p[4]), cB1 = __expf(p[5]), cB2 = __expf(p[6]), cB3 = __expf(p[7]);
        s0 += cA0 + cB0;
        s1 += cA1 + cB1;
        s2 += cA2 + cB2;
        s3 += cA3 + cB3;
        a0 = fmaf(cA0, vA.x, fmaf(cB0, vB.x, a0));
        a1 = fmaf(cA1, vA.y, fmaf(cB1, vB.y, a1));
        a2 = fmaf(cA2, vA.z, fmaf(cB2, vB.z, a2));
        a3 = fmaf(cA3, vA.w, fmaf(cB3, vB.w, a3));
    }
    if (e < e1) {
        int sA = __ldg(&g_csrc[e]);
        float4 vA = __ldg(reinterpret_cast<const float4*>(&g_xl[sA * DD + lane * 4]));
        float p[4];
        p[0] = lrelu(vA.x + xr.x) * av0;
        p[1] = lrelu(vA.y + xr.y) * av1;
        p[2] = lrelu(vA.z + xr.z) * av2;
        p[3] = lrelu(vA.w + xr.w) * av3;
        #pragma unroll
        for (int o = 16; o > 0; o >>= 1) {
            #pragma unroll
            for (int i = 0; i < 4; i++)
                p[i] += __shfl_xor_sync(0xFFFFFFFFu, p[i], o);
        }
        float c0 = __expf(p[0]), c1 = __expf(p[1]), c2 = __expf(p[2]), c3 = __expf(p[3]);
        s0 += c0; s1 += c1; s2 += c2; s3 += c3;
        a0 = fmaf(c0, vA.x, a0);
        a1 = fmaf(c1, vA.y, a1);
        a2 = fmaf(c2, vA.z, a2);
        a3 = fmaf(c3, vA.w, a3);
    }

    // residual + bias (permuted layout), then LayerNorm + ReLU
    float4 rsd = *reinterpret_cast<const float4*>(&g_res[d * DD + lane * 4]);
    float o0 = a0 / s0 + rsd.x;
    float o1 = a1 / s1 + rsd.y;
    float o2 = a2 / s2 + rsd.z;
    float o3 = a3 / s3 + rsd.w;

    float sum = o0 + o1 + o2 + o3;
    #pragma unroll
    for (int off = 16; off > 0; off >>= 1)
        sum += __shfl_xor_sync(0xFFFFFFFFu, sum, off);
    float mu = sum * (1.f / 128.f);

    float var = (o0 - mu) * (o0 - mu) + (o1 - mu) * (o1 - mu)
              + (o2 - mu) * (o2 - mu) + (o3 - mu) * (o3 - mu);
    #pragma unroll
    for (int off = 16; off > 0; off >>= 1)
        var += __shfl_xor_sync(0xFFFFFFFFu, var, off);
    var *= (1.f / 128.f);
    float rs = rsqrtf(var + 1e-5f);

    // write standard layout: head h at column h*32+lane
    {
        int c0 = lane;
        float y0 = (o0 - mu) * rs * gam[c0] + bet[c0];
        out[d * DD + c0] = fmaxf(y0, 0.f);
        int c1 = 32 + lane;
        float y1 = (o1 - mu) * rs * gam[c1] + bet[c1];
        out[d * DD + c1] = fmaxf(y1, 0.f);
        int c2 = 64 + lane;
        float y2 = (o2 - mu) * rs * gam[c2] + bet[c2];
        out[d * DD + c2] = fmaxf(y2, 0.f);
        int c3 = 96 + lane;
        float y3 = (o3 - mu) * rs * gam[c3] + bet[c3];
        out[d * DD + c3] = fmaxf(y3, 0.f);
    }
}

// ============================ launch ============================

extern "C" void kernel_launch(void* const* d_in, const int* in_sizes, int n_in,
                              void* d_out, int out_size) {
    const float* x     = (const float*)d_in[0];
    const int*   ei    = (const int*)  d_in[1];
    const float* Wl0   = (const float*)d_in[2];
    const float* bl0   = (const float*)d_in[3];
    const float* Wr0   = (const float*)d_in[4];
    const float* br0   = (const float*)d_in[5];
    const float* att0  = (const float*)d_in[6];
    const float* Wres0 = (const float*)d_in[7];
    const float* bias0 = (const float*)d_in[8];
    const float* g0    = (const float*)d_in[9];
    const float* be0   = (const float*)d_in[10];
    const float* Wl1   = (const float*)d_in[11];
    const float* bl1   = (const float*)d_in[12];
    const float* Wr1   = (const float*)d_in[13];
    const float* br1   = (const float*)d_in[14];
    const float* att1  = (const float*)d_in[15];
    const float* Wres1 = (const float*)d_in[16];
    const float* bias1 = (const float*)d_in[17];
    const float* g1    = (const float*)d_in[18];
    const float* be1   = (const float*)d_in[19];
    float* out = (float*)d_out;

    const int NB = (NN + 2047) / 2048;   // 25
    zero_cnt_kernel<<<(NN + 255) / 256, 256>>>();
    hist_kernel<<<(NEE + 255) / 256, 256>>>(ei);
    scan1_kernel<<<NB, 1024>>>();
    scan2_kernel<<<1, 32>>>(NB);
    scan3_kernel<<<(NN + 255) / 256, 256>>>();
    scatter_kernel<<<(NEE + 255) / 256, 256>>>(ei);

    dim3 gb((NN + GM - 1) / GM, 3);
    int eb = NN / 8;  // 8 warps per block, exact

    gemm3_kernel<<<gb, 256>>>(x, Wl0, bl0, Wr0, br0, Wres0, bias0);
    edge_kernel<<<eb, 256>>>(att0, g0, be0, nullptr);

    gemm3_kernel<<<gb, 256>>>(nullptr, Wl1, bl1, Wr1, br1, Wres1, bias1);
    edge_kernel<<<eb, 256>>>(att1, g1, be1, out);
}

// round 4
// speedup vs baseline: 2.5428x; 1.3179x over previous
#include <cuda_runtime.h>
#include <math_constants.h>

#define NN 50000
#define NE 800000
#define NEE 850000          // NE + NN self loops
#define DD 128
#define HH 4

// ---- scratch (device globals; no allocations allowed) ----
// All node tensors in STANDARD head-major layout: (h, c) at offset h*32 + c.
__device__ float g_xl[NN * DD];
__device__ float g_xr[NN * DD];
__device__ float g_res[NN * DD];
__device__ float g_h[NN * DD];
__device__ int   g_rowptr[NN + 1];
__device__ int   g_cnt[NN];
__device__ int   g_off[NN];
__device__ int   g_csrc[NEE];
__device__ int   g_bsum[32];
__device__ int   g_boff[32];

// ============================ CSR build ============================

__global__ void zero_cnt_kernel() {
    int i = blockIdx.x * blockDim.x + threadIdx.x;
    if (i < NN) g_cnt[i] = 0;
}

__global__ void hist_kernel(const int* __restrict__ ei) {
    int e = blockIdx.x * blockDim.x + threadIdx.x;
    if (e >= NEE) return;
    int dst = (e < NE) ? ei[NE + e] : (e - NE);
    atomicAdd(&g_cnt[dst], 1);
}

__global__ void scan1_kernel() {
    __shared__ int sh[1024];
    int tid = threadIdx.x;
    int base = blockIdx.x * 2048;
    int i0 = base + 2 * tid;
    int a = (i0     < NN) ? g_cnt[i0]     : 0;
    int b = (i0 + 1 < NN) ? g_cnt[i0 + 1] : 0;
    int pair = a + b;
    sh[tid] = pair;
    __syncthreads();
    #pragma unroll
    for (int o = 1; o < 1024; o <<= 1) {
        int t = (tid >= o) ? sh[tid - o] : 0;
        __syncthreads();
        sh[tid] += t;
        __syncthreads();
    }
    int excl = sh[tid] - pair;
    if (i0     < NN) g_rowptr[i0]     = excl;
    if (i0 + 1 < NN) g_rowptr[i0 + 1] = excl + a;
    if (tid == 1023) g_bsum[blockIdx.x] = sh[1023];
}

__global__ void scan2_kernel(int nb) {
    int lane = threadIdx.x;
    int v = (lane < nb) ? g_bsum[lane] : 0;
    int orig = v;
    #pragma unroll
    for (int o = 1; o < 32; o <<= 1) {
        int t = __shfl_up_sync(0xFFFFFFFFu, v, o);
        if (lane >= o) v += t;
    }
    if (lane < nb) g_boff[lane] = v - orig;
    if (lane == nb - 1) g_rowptr[NN] = v;
}

__global__ void scan3_kernel() {
    int i = blockIdx.x * blockDim.x + threadIdx.x;
    if (i >= NN) return;
    int r = g_rowptr[i] + g_boff[i >> 11];
    g_rowptr[i] = r;
    g_off[i] = r;
}

__global__ void scatter_kernel(const int* __restrict__ ei) {
    int e = blockIdx.x * blockDim.x + threadIdx.x;
    if (e >= NEE) return;
    int src, dst;
    if (e < NE) { src = ei[e]; dst = ei[NE + e]; }
    else        { src = e - NE; dst = e - NE; }
    int pos = atomicAdd(&g_off[dst], 1);
    g_csrc[pos] = src;
}

// ==================== fused triple GEMM (tf32 tensor core) ====================

#define GM 128
#define GK 32
#define XS_STR 36     // 32 + 4 pad
#define WS_STR 136    // 128 + 8 pad

__device__ __forceinline__ unsigned f2tf32(float x) {
    unsigned u;
    asm("cvt.rna.tf32.f32 %0, %1;" : "=r"(u) : "f"(x));
    return u;
}

__device__ __forceinline__ void mma_tf32(float* d, const unsigned* a, const unsigned* b) {
    asm volatile(
        "mma.sync.aligned.m16n8k8.row.col.f32.tf32.tf32.f32 "
        "{%0,%1,%2,%3}, {%4,%5,%6,%7}, {%8,%9}, {%0,%1,%2,%3};"
        : "+f"(d[0]), "+f"(d[1]), "+f"(d[2]), "+f"(d[3])
        : "r"(a[0]), "r"(a[1]), "r"(a[2]), "r"(a[3]), "r"(b[0]), "r"(b[1]));
}

__global__ void __launch_bounds__(256, 2)
gemm3_kernel(const float* __restrict__ xin,
             const float* __restrict__ W0, const float* __restrict__ b0,
             const float* __restrict__ W1, const float* __restrict__ b1,
             const float* __restrict__ W2, const float* __restrict__ b2) {
    const float* x = xin ? xin : g_h;
    const float* W;
    const float* bias;
    float* out;
    if (blockIdx.y == 0)      { W = W0; bias = b0; out = g_xl; }
    else if (blockIdx.y == 1) { W = W1; bias = b1; out = g_xr; }
    else                      { W = W2; bias = b2; out = g_res; }

    __shared__ float xs[GM][XS_STR];
    __shared__ float ws[GK][WS_STR];

    int tid  = threadIdx.x;
    int lane = tid & 31;
    int wid  = tid >> 5;
    int wm   = wid & 3;
    int wn   = wid >> 2;
    int g    = lane >> 2;
    int t4   = lane & 3;
    int m0   = blockIdx.x * GM;

    float acc[2][8][4];
    #pragma unroll
    for (int mt = 0; mt < 2; mt++)
        #pragma unroll
        for (int nt = 0; nt < 8; nt++)
            #pragma unroll
            for (int i = 0; i < 4; i++) acc[mt][nt][i] = 0.f;

    for (int kc = 0; kc < DD; kc += GK) {
        #pragma unroll
        for (int t = 0; t < 4; t++) {
            int f   = tid + t * 256;
            int row = f >> 3;
            int c4  = f & 7;
            int m   = m0 + row;
            float4 v = make_float4(0.f, 0.f, 0.f, 0.f);
            if (m < NN)
                v = *reinterpret_cast<const float4*>(&x[m * DD + kc + c4 * 4]);
            float* dst = &xs[row][c4 * 4];
            dst[0] = __uint_as_float(f2tf32(v.x));
            dst[1] = __uint_as_float(f2tf32(v.y));
            dst[2] = __uint_as_float(f2tf32(v.z));
            dst[3] = __uint_as_float(f2tf32(v.w));
        }
        #pragma unroll
        for (int t = 0; t < 4; t++) {
            int f   = tid + t * 256;
            int row = f >> 5;
            int c4  = f & 31;
            float4 v = *reinterpret_cast<const float4*>(&W[(kc + row) * DD + c4 * 4]);
            float* dst = &ws[row][c4 * 4];
            dst[0] = __uint_as_float(f2tf32(v.x));
            dst[1] = __uint_as_float(f2tf32(v.y));
            dst[2] = __uint_as_float(f2tf32(v.z));
            dst[3] = __uint_as_float(f2tf32(v.w));
        }
        __syncthreads();

        #pragma unroll
        for (int ks = 0; ks < GK; ks += 8) {
            unsigned A[2][4];
            #pragma unroll
            for (int mt = 0; mt < 2; mt++) {
                int r0 = wm * 32 + mt * 16;
                A[mt][0] = __float_as_uint(xs[r0 + g    ][ks + t4    ]);
                A[mt][1] = __float_as_uint(xs[r0 + 8 + g][ks + t4    ]);
                A[mt][2] = __float_as_uint(xs[r0 + g    ][ks + t4 + 4]);
                A[mt][3] = __float_as_uint(xs[r0 + 8 + g][ks + t4 + 4]);
            }
            unsigned B[8][2];
            #pragma unroll
            for (int nt = 0; nt < 8; nt++) {
                int c0 = wn * 64 + nt * 8 + g;
                B[nt][0] = __float_as_uint(ws[ks + t4    ][c0]);
                B[nt][1] = __float_as_uint(ws[ks + t4 + 4][c0]);
            }
            #pragma unroll
            for (int mt = 0; mt < 2; mt++)
                #pragma unroll
                for (int nt = 0; nt < 8; nt++)
                    mma_tf32(acc[mt][nt], A[mt], B[nt]);
        }
        __syncthreads();
    }

    #pragma unroll
    for (int mt = 0; mt < 2; mt++) {
        #pragma unroll
        for (int nt = 0; nt < 8; nt++) {
            int r = m0 + wm * 32 + mt * 16 + g;
            int c = wn * 64 + nt * 8 + t4 * 2;
            float bv0 = bias[c], bv1 = bias[c + 1];
            if (r < NN) {
                out[r * DD + c]     = acc[mt][nt][0] + bv0;
                out[r * DD + c + 1] = acc[mt][nt][1] + bv1;
            }
            if (r + 8 < NN) {
                out[(r + 8) * DD + c]     = acc[mt][nt][2] + bv0;
                out[(r + 8) * DD + c + 1] = acc[mt][nt][3] + bv1;
            }
        }
    }
}

// ================= fused edge kernel: group-of-8 score reduction =================
// Standard head-major layout. Lane L owns head L>>3, channels (L&7)*4..+3.
// Score dot per head lives in an 8-lane group -> one 3-level shfl tree for all
// 4 heads at once, 1 exp per lane. Fused residual + LayerNorm + ReLU epilogue.

__device__ __forceinline__ float lrelu(float t) {
    return t > 0.f ? t : 0.2f * t;
}

__global__ void edge_kernel(const float* __restrict__ att,
                            const float* __restrict__ gam,
                            const float* __restrict__ bet,
                            float* outp /* null -> g_h */) {
    float* out = outp ? outp : g_h;
    int d = (blockIdx.x * blockDim.x + threadIdx.x) >> 5;
    int lane = threadIdx.x & 31;
    if (d >= NN) return;

    float4 xr = *reinterpret_cast<const float4*>(&g_xr[d * DD + lane * 4]);
    float4 at = __ldg(reinterpret_cast<const float4*>(&att[lane * 4]));

    float s = 0.f;
    float a0 = 0.f, a1 = 0.f, a2 = 0.f, a3 = 0.f;

    int e0 = g_rowptr[d], e1 = g_rowptr[d + 1];
    int e = e0;
    for (; e + 2 <= e1; e += 2) {
        int sA = __ldg(&g_csrc[e]);
        int sB = __ldg(&g_csrc[e + 1]);
        float4 vA = __ldg(reinterpret_cast<const float4*>(&g_xl[sA * DD + lane * 4]));
        float4 vB = __ldg(reinterpret_cast<const float4*>(&g_xl[sB * DD + lane * 4]));

        float pA = lrelu(vA.x + xr.x) * at.x;
        pA = fmaf(lrelu(vA.y + xr.y), at.y, pA);
        pA = fmaf(lrelu(vA.z + xr.z), at.z, pA);
        pA = fmaf(lrelu(vA.w + xr.w), at.w, pA);
        float pB = lrelu(vB.x + xr.x) * at.x;
        pB = fmaf(lrelu(vB.y + xr.y), at.y, pB);
        pB = fmaf(lrelu(vB.z + xr.z), at.z, pB);
        pB = fmaf(lrelu(vB.w + xr.w), at.w, pB);

        // reduce within 8-lane group (all 4 heads simultaneously)
        #pragma unroll
        for (int o = 4; o > 0; o >>= 1) {
            pA += __shfl_xor_sync(0xFFFFFFFFu, pA, o);
            pB += __shfl_xor_sync(0xFFFFFFFFu, pB, o);
        }
        float cA = __expf(pA);
        float cB = __expf(pB);
        s += cA + cB;
        a0 = fmaf(cA, vA.x, fmaf(cB, vB.x, a0));
        a1 = fmaf(cA, vA.y, fmaf(cB, vB.y, a1));
        a2 = fmaf(cA, vA.z, fmaf(cB, vB.z, a2));
        a3 = fmaf(cA, vA.w, fmaf(cB, vB.w, a3));
    }
    if (e < e1) {
        int sA = __ldg(&g_csrc[e]);
        float4 vA = __ldg(reinterpret_cast<const float4*>(&g_xl[sA * DD + lane * 4]));
        float pA = lrelu(vA.x + xr.x) * at.x;
        pA = fmaf(lrelu(vA.y + xr.y), at.y, pA);
        pA = fmaf(lrelu(vA.z + xr.z), at.z, pA);
        pA = fmaf(lrelu(vA.w + xr.w), at.w, pA);
        #pragma unroll
        for (int o = 4; o > 0; o >>= 1)
            pA += __shfl_xor_sync(0xFFFFFFFFu, pA, o);
        float cA = __expf(pA);
        s += cA;
        a0 = fmaf(cA, vA.x, a0);
        a1 = fmaf(cA, vA.y, a1);
        a2 = fmaf(cA, vA.z, a2);
        a3 = fmaf(cA, vA.w, a3);
    }

    // residual + bias, then LayerNorm + ReLU (all standard layout)
    float4 rsd = *reinterpret_cast<const float4*>(&g_res[d * DD + lane * 4]);
    float inv = 1.f / s;
    float o0 = a0 * inv + rsd.x;
    float o1 = a1 * inv + rsd.y;
    float o2 = a2 * inv + rsd.z;
    float o3 = a3 * inv + rsd.w;

    float sum = o0 + o1 + o2 + o3;
    #pragma unroll
    for (int off = 16; off > 0; off >>= 1)
        sum += __shfl_xor_sync(0xFFFFFFFFu, sum, off);
    float mu = sum * (1.f / 128.f);

    float var = (o0 - mu) * (o0 - mu) + (o1 - mu) * (o1 - mu)
              + (o2 - mu) * (o2 - mu) + (o3 - mu) * (o3 - mu);
    #pragma unroll
    for (int off = 16; off > 0; off >>= 1)
        var += __shfl_xor_sync(0xFFFFFFFFu, var, off);
    var *= (1.f / 128.f);
    float rs = rsqrtf(var + 1e-5f);

    float4 gm = __ldg(reinterpret_cast<const float4*>(&gam[lane * 4]));
    float4 bt = __ldg(reinterpret_cast<const float4*>(&bet[lane * 4]));
    float4 y;
    y.x = fmaxf((o0 - mu) * rs * gm.x + bt.x, 0.f);
    y.y = fmaxf((o1 - mu) * rs * gm.y + bt.y, 0.f);
    y.z = fmaxf((o2 - mu) * rs * gm.z + bt.z, 0.f);
    y.w = fmaxf((o3 - mu) * rs * gm.w + bt.w, 0.f);
    *reinterpret_cast<float4*>(&out[d * DD + lane * 4]) = y;
}

// ============================ launch ============================

extern "C" void kernel_launch(void* const* d_in, const int* in_sizes, int n_in,
                              void* d_out, int out_size) {
    const float* x     = (const float*)d_in[0];
    const int*   ei    = (const int*)  d_in[1];
    const float* Wl0   = (const float*)d_in[2];
    const float* bl0   = (const float*)d_in[3];
    const float* Wr0   = (const float*)d_in[4];
    const float* br0   = (const float*)d_in[5];
    const float* att0  = (const float*)d_in[6];
    const float* Wres0 = (const float*)d_in[7];
    const float* bias0 = (const float*)d_in[8];
    const float* g0    = (const float*)d_in[9];
    const float* be0   = (const float*)d_in[10];
    const float* Wl1   = (const float*)d_in[11];
    const float* bl1   = (const float*)d_in[12];
    const float* Wr1   = (const float*)d_in[13];
    const float* br1   = (const float*)d_in[14];
    const float* att1  = (const float*)d_in[15];
    const float* Wres1 = (const float*)d_in[16];
    const float* bias1 = (const float*)d_in[17];
    const float* g1    = (const float*)d_in[18];
    const float* be1   = (const float*)d_in[19];
    float* out = (float*)d_out;

    const int NB = (NN + 2047) / 2048;   // 25
    zero_cnt_kernel<<<(NN + 255) / 256, 256>>>();
    hist_kernel<<<(NEE + 255) / 256, 256>>>(ei);
    scan1_kernel<<<NB, 1024>>>();
    scan2_kernel<<<1, 32>>>(NB);
    scan3_kernel<<<(NN + 255) / 256, 256>>>();
    scatter_kernel<<<(NEE + 255) / 256, 256>>>(ei);

    dim3 gb((NN + GM - 1) / GM, 3);
    int eb = NN / 8;  // 8 warps per block, exact

    gemm3_kernel<<<gb, 256>>>(x, Wl0, bl0, Wr0, br0, Wres0, bias0);
    edge_kernel<<<eb, 256>>>(att0, g0, be0, nullptr);

    gemm3_kernel<<<gb, 256>>>(nullptr, Wl1, bl1, Wr1, br1, Wres1, bias1);
    edge_kernel<<<eb, 256>>>(att1, g1, be1, out);
}